// round 10
// baseline (speedup 1.0000x reference)
#include <cuda_runtime.h>
#include <cstdint>

typedef unsigned long long ull;

// Problem constants
#define BT   512          // batches
#define TT   4096         // timesteps
#define CH   64           // steps per chunk
#define NCH  (TT / CH)    // 64 chunks
#define NBLK 16           // blocks (each fully independent)
#define BPB  32           // batches per block
#define NTHR 128          // 4 warps

#define DT_F     0.001f
#define C_F      1.6970562748477140f      // sqrt(4*ETA*KAPPA) = sqrt(2.88)
#define NDTC2    (-0.00288f)              // -DT * C^2
#define KX_F     (1.0f - 0.00015f)        // 1 - 0.5*GAMMA*DT
#define KCOV_F   (1.0f - 0.0003f)         // 1 - GAMMA*DT
#define DTD_F    (0.00165f)               // DT * (GAMMA*(NBAR+0.5)+KAPPA)
#define CDT_F    (C_F * DT_F)

// smem layout (bytes):
//   dyS : float2[3][32][66] = 50688   (ring of 3; row 528B, cp.async-aligned)
//   cfS : float4[2][64]     =  2048   @ 50688
//   oS  : float [2][32*66]  = 16896   @ 52736
//   rawS: float2[3][64]     =  1536   @ 69632  (riccati raw (vx,cxp) ring)
//   finS: float4            =    16   @ 71168
#define DYS_BUF_F2  2112
#define OS_BUF_F    2112
#define SMEM_CF_OFF 50688
#define SMEM_OS_OFF 52736
#define SMEM_RAW    69632
#define SMEM_FIN    71168
#define SMEM_TOTAL  71200

static __device__ __forceinline__ uint32_t smem_u32(const void* p) {
    uint32_t a;
    asm("{ .reg .u64 t; cvta.to.shared.u64 t, %1; cvt.u32.u64 %0, t; }" : "=r"(a) : "l"(p));
    return a;
}
static __device__ __forceinline__ void cp_async16(uint32_t dst, const void* src) {
    asm volatile("cp.async.cg.shared.global [%0], [%1], 16;" :: "r"(dst), "l"(src));
}
#define CP_COMMIT() asm volatile("cp.async.commit_group;" ::: "memory")
#define CP_WAIT1()  asm volatile("cp.async.wait_group 1;" ::: "memory")
#define CP_WAIT0()  asm volatile("cp.async.wait_group 0;" ::: "memory")

#define F32X2_FMA(out, a, b, c) \
    asm("fma.rn.f32x2 %0, %1, %2, %3;" : "=l"(out) : "l"(a), "l"(b), "l"(c))
#define PACK2(out, lo, hi) \
    asm("mov.b64 %0, {%1, %2};" : "=l"(out) : "f"(lo), "f"(hi))
#define UNPACK2(lo, hi, in) \
    asm("mov.b64 {%0, %1}, %2;" : "=f"(lo), "=f"(hi) : "l"(in))

__global__ void __launch_bounds__(NTHR)
grnn_kernel(const float* __restrict__ dy,
            const float* __restrict__ state0,
            const float* __restrict__ omega_p,
            float*       __restrict__ out)
{
    extern __shared__ char sm[];
    float2* dyS  = reinterpret_cast<float2*>(sm);                 // [3][32][66]
    float4* cfS  = reinterpret_cast<float4*>(sm + SMEM_CF_OFF);   // [2][64]
    float*  oS   = reinterpret_cast<float*>(sm + SMEM_OS_OFF);    // [2][2112]
    float2* rawS = reinterpret_cast<float2*>(sm + SMEM_RAW);      // [3][64]
    float4* finS = reinterpret_cast<float4*>(sm + SMEM_FIN);

    const int tid  = threadIdx.x;
    const int lane = tid & 31;
    const int wid  = tid >> 5;
    const int xb   = blockIdx.x;
    const int b    = xb * BPB + lane;

    const float w     = omega_p[0];
    const float wdt   = w * DT_F;
    const float nwdt  = -wdt;
    const float w2dt  = 2.0f * wdt;
    const float nw2dt = -w2dt;
    ull W2W; PACK2(W2W, w2dt, wdt);     // packed (w2dt, wdt)

    const float2* dyb = reinterpret_cast<const float2*>(dy) + (size_t)b * TT;
    float2*       dyh = reinterpret_cast<float2*>(out + 6 * BT);

    // Per-warp persistent state
    float x0 = 0.f, x1 = 0.f;           // w0
    ull   vc = 0;  float vp = 0.f;      // w1 lane0: packed (vx,cxp), scalar vp

    // Riccati raw chunk p: write pre-update (vx,cxp) pairs into rawS slot p%3
    auto riccati_raw = [&](int p) {
        ull* rg = reinterpret_cast<ull*>(rawS + (p % 3) * CH);
#pragma unroll 16
        for (int s = 0; s < CH; ++s) {
            rg[s] = vc;                               // STS.64 of packed pre-update
            float vx, cxp; UNPACK2(vx, cxp, vc);
            const float m = fmaf(NDTC2, vx, KCOV_F);  // 1 - 0.3DT - DT c^2 vx
            const float t = nwdt * vx;                // -wdt*vx
            ull cv;  PACK2(cv,  cxp,   vp);
            ull dt2; PACK2(dt2, DTD_F, t);
            ull gh;  F32X2_FMA(gh, W2W, cv, dt2);     // (g, h)
            ull mm;  PACK2(mm, m, m);
            ull nvc; F32X2_FMA(nvc, mm, vc, gh);      // (nvx, ncxp)
            const float u = fmaf(NDTC2, cxp, nw2dt);
            const float q = fmaf(u, cxp, DTD_F);
            vp = fmaf(KCOV_F, vp, q);
            vc = nvc;
        }
    };

    // Derive float4 coefs for chunk p from rawS (32 lanes x 2 steps)
    auto derive = [&](int p) {
        const float4 r = *reinterpret_cast<const float4*>(&rawS[(p % 3) * CH + 2 * lane]);
        float4* cg = cfS + (p & 1) * CH;
        cg[2 * lane]     = make_float4(fmaf(NDTC2, r.x, KX_F), fmaf(NDTC2, r.y, nwdt),
                                       C_F * r.x, C_F * r.y);
        cg[2 * lane + 1] = make_float4(fmaf(NDTC2, r.z, KX_F), fmaf(NDTC2, r.w, nwdt),
                                       C_F * r.z, C_F * r.w);
    };

    // Stage dy chunk c into ring slot c%3 (one commit group)
    auto stage = [&](int c) {
        const float2*  src = dyb + c * CH;
        const uint32_t dst = smem_u32(&dyS[(c % 3) * DYS_BUF_F2 + lane * 66]);
#pragma unroll
        for (int k = 0; k < CH / 2; ++k) cp_async16(dst + k * 16, src + 2 * k);
        CP_COMMIT();
    };

    // Flush staged dy_hat chunk fc: batch 8 LDS into regs, then 8 STG.128
    auto flush = [&](int fc) {
        const float* ou = &oS[(fc & 1) * OS_BUF_F + lane * 66];
        float2* fb = dyh + (size_t)(xb * BPB) * TT + fc * CH + 2 * lane;
#pragma unroll
        for (int g = 0; g < 4; ++g) {
            float2 v[8];
#pragma unroll
            for (int i = 0; i < 8; ++i)
                v[i] = *reinterpret_cast<const float2*>(&ou[2 * (8 * g + i)]);
#pragma unroll
            for (int i = 0; i < 8; ++i)
                *reinterpret_cast<float4*>(fb + (size_t)(8 * g + i) * TT) =
                    make_float4(v[i].x, 0.f, v[i].y, 0.f);
        }
    };

    // ---------------- prologue ----------------
    if (wid == 0) {
        x0 = state0[(size_t)b * 6 + 0];
        x1 = state0[(size_t)b * 6 + 1];
    } else if (wid == 1 && lane == 0) {
        float vx  = state0[2];
        float cxp = state0[4];
        vp = state0[3];
        PACK2(vc, vx, cxp);
        riccati_raw(0);
        riccati_raw(1);
    } else if (wid == 2) {
        stage(0);
        stage(1);
    }
    __syncthreads();
    if (wid == 2) {
        derive(0);           // cf chunk 0 from raw0
        CP_WAIT1();          // dy chunk 0 resident
    }
    __syncthreads();

    // ---------------- main loop ----------------
    for (int c = 0; c < NCH; ++c) {
        if (wid == 0) {
            // x-chain: 4-step groups, register double-buffered prefetch
            // (buffer = kc[4]+kn[4]+dc[2]+dn[2] = 48 regs -> fits, no demotion;
            //  4-step chain = 32 cyc >= 29-cyc LDS latency -> loads hidden)
            const float4* cf  = cfS + (c & 1) * CH;
            const float4* dr4 = reinterpret_cast<const float4*>(
                                    &dyS[(c % 3) * DYS_BUF_F2 + lane * 66]);
            float* ou = &oS[(c & 1) * OS_BUF_F] + 2 * lane;

            float4 ka[4], kb[4], da[2], db[2];
#pragma unroll
            for (int s = 0; s < 4; ++s) ka[s] = cf[s];
            da[0] = dr4[0]; da[1] = dr4[1];

#pragma unroll
            for (int j = 0; j < 16; ++j) {
                float4* kc = (j & 1) ? kb : ka;
                float4* dc = (j & 1) ? db : da;
                float4* kn = (j & 1) ? ka : kb;
                float4* dn = (j & 1) ? da : db;
                if (j < 15) {                   // issue next group's loads NOW
#pragma unroll
                    for (int s = 0; s < 4; ++s) kn[s] = cf[4 * (j + 1) + s];
                    dn[0] = dr4[2 * (j + 1)];
                    dn[1] = dr4[2 * (j + 1) + 1];
                }
#pragma unroll
                for (int s = 0; s < 4; ++s) {
                    const int    st = 4 * j + s;
                    const float4 k  = kc[s];
                    const float  d  = (s & 1) ? dc[s >> 1].z : dc[s >> 1].x;
                    ou[(st >> 1) * 66 + (st & 1)] = CDT_F * x0;   // PRE-update x
                    const float nx0 = fmaf(k.x, x0, fmaf(wdt,  x1, k.z * d));
                    const float nx1 = fmaf(k.y, x0, fmaf(KX_F, x1, k.w * d));
                    x0 = nx0; x1 = nx1;
                }
            }
        } else if (wid == 1) {
            if (lane == 0 && c + 2 < NCH) {
                riccati_raw(c + 2);
                if (c + 2 == NCH - 1) {        // state now final (post step TT)
                    float vx, cxp; UNPACK2(vx, cxp, vc);
                    *finS = make_float4(vx, vp, cxp, state0[5] + DT_F * (float)TT);
                }
            }
        } else if (wid == 2) {
            if (c + 2 < NCH)      { stage(c + 2); CP_WAIT1(); }   // chunk c+1 resident
            else if (c + 2 == NCH) CP_WAIT0();                    // drain last chunk
            if (c + 1 < NCH) derive(c + 1);    // coefs for next chunk from raw ring
        } else {  // wid == 3
            if (c >= 1) flush(c - 1);
        }
        __syncthreads();
    }

    // ---------------- epilogue ----------------
    if (wid == 3) {
        flush(NCH - 1);
    } else if (wid == 0) {
        const float4 f = *finS;
        float* fs = out + (size_t)b * 6;
        fs[0] = x0;
        fs[1] = x1;
        fs[2] = f.x;   // vx  = ncov[0,0]
        fs[3] = f.y;   // vp  = ncov[1,1]
        fs[4] = f.z;   // cxp = ncov[1,0]
        fs[5] = f.w;   // t
    }
}

extern "C" void kernel_launch(void* const* d_in, const int* in_sizes, int n_in,
                              void* d_out, int out_size)
{
    const float* dy      = (const float*)d_in[0];
    const float* state0  = (const float*)d_in[1];
    const float* omega_p = (const float*)d_in[2];
    float*       out     = (float*)d_out;
    (void)in_sizes; (void)n_in; (void)out_size;

    cudaFuncSetAttribute(grnn_kernel,
                         cudaFuncAttributeMaxDynamicSharedMemorySize, SMEM_TOTAL);
    grnn_kernel<<<NBLK, NTHR, SMEM_TOTAL>>>(dy, state0, omega_p, out);
}